// round 2
// baseline (speedup 1.0000x reference)
#include <cuda_runtime.h>
#include <math.h>

// ---------------------------------------------------------------------------
// AliasFreeConv: modulated 3x3 conv (demodulated) + 2x up (12-tap separable)
// + leaky relu + 2x down (12-tap separable).  B=8, C=512->512, 64x64 input.
//
// Restructure: w[b,co,ci,k] = conv_w * (wscale*s[b,ci]) * demod[b,co]
//   -> scale input per (b,ci), conv with SHARED conv_w, scale output per (b,co)
// ---------------------------------------------------------------------------

#define BATCH   8
#define CH      512           // C_IN == C_OUT
#define HW      64
#define OHW     62            // after VALID 3x3
#define BC      (BATCH * CH)  // 4096
#define TAPS    12

#define LIN_SCALE 0.04419417382415922f     // 1/sqrt(512)
#define WSCALE    0.014731391274719738f    // 1/sqrt(512*9)
#define NEG_SLOPE 0.2f
#define LRELU_SCALE 1.4142135623730951f
#define EPS_F   1e-8f

// ------------------------- scratch (device globals) ------------------------
__device__ float g_sscale[BC];                       // wscale * s[b,ci]
__device__ float g_dscale[BC];                       // demod[b,co]
__device__ float g_wsq[CH * CH];                     // wsq[ci*512 + co]
__device__ float g_conv[(size_t)BC * OHW * OHW];     // [bc][62][62]
__device__ float g_up2 [(size_t)BC * 128 * 128];     // [bc][128][128]
__device__ float g_bufA[(size_t)BC * 128 * 64];      // up1 [bc][62][128] / dn1 [bc][128][64]

// ------------------------------ modulation ---------------------------------
__global__ void mod_kernel(const float* __restrict__ style,
                           const float* __restrict__ mod_w,
                           const float* __restrict__ mod_b)
{
    int b  = blockIdx.x;
    int ci = threadIdx.x;
    const float* st = style + b * CH;
    const float* mw = mod_w + ci * CH;
    float acc = 0.f;
    for (int k = 0; k < CH; k++) acc += st[k] * mw[k];
    float s = acc * LIN_SCALE + mod_b[ci];
    g_sscale[b * CH + ci] = WSCALE * s;
}

// wsq[ci*512+co] = sum_k conv_w[co,ci,k]^2
__global__ void wsq_kernel(const float* __restrict__ conv_w)
{
    int id = blockIdx.x * blockDim.x + threadIdx.x;
    if (id >= CH * CH) return;
    int co = id & (CH - 1);
    int ci = id >> 9;
    const float* w = conv_w + (size_t)co * CH * 9 + ci * 9;
    float acc = 0.f;
#pragma unroll
    for (int k = 0; k < 9; k++) acc += w[k] * w[k];
    g_wsq[ci * CH + co] = acc;
}

// dscale[b,co] = rsqrt( sum_ci wsq[ci,co] * sscale[b,ci]^2 + eps )
__global__ void demod_kernel()
{
    int id = blockIdx.x * blockDim.x + threadIdx.x;
    if (id >= BATCH * CH) return;
    int co = id & (CH - 1);
    int b  = id >> 9;
    float acc = 0.f;
    for (int ci = 0; ci < CH; ci++) {
        float ss = g_sscale[b * CH + ci];
        acc += g_wsq[ci * CH + co] * (ss * ss);
    }
    g_dscale[id] = 1.0f / sqrtf(acc + EPS_F);
}

// ------------------------------- conv --------------------------------------
// Block: 64 couts x (16x16 px) for one (b, coblk, tile).  CI=8 channel chunk.
// Thread: 8 couts x 8 px register tile.
#define CI_CHUNK 8

__global__ __launch_bounds__(256)
void conv_kernel(const float* __restrict__ x,
                 const float* __restrict__ conv_w,
                 const float* __restrict__ act_b)
{
    __shared__ float xs[CI_CHUNK][18][18];
    __shared__ float ws[CI_CHUNK * 9][65];   // stride 65: conflict-free

    int t     = threadIdx.x;
    int ox0   = blockIdx.x * 16;
    int oy0   = blockIdx.y * 16;
    int z     = blockIdx.z;            // b*8 + coblk
    int b     = z >> 3;
    int co0   = (z & 7) * 64;

    int cg      = t >> 5;              // 0..7 -> cout group
    int pxg     = t & 31;              // 0..31 -> pixel group
    int co_base = cg * 8;
    int row     = pxg >> 1;            // 0..15
    int col0    = (pxg & 1) * 8;       // 0 or 8

    float acc[8][8];
#pragma unroll
    for (int i = 0; i < 8; i++)
#pragma unroll
        for (int j = 0; j < 8; j++) acc[i][j] = 0.f;

    const float* xb = x + (size_t)b * CH * HW * HW;
    const float* ssb = g_sscale + b * CH;

    for (int ci0 = 0; ci0 < CH; ci0 += CI_CHUNK) {
        __syncthreads();
        // load input tile (scaled by per-channel modulation)
        for (int e = t; e < CI_CHUNK * 18 * 18; e += 256) {
            int cl  = e / 324;
            int rem = e - cl * 324;
            int r   = rem / 18;
            int c   = rem - r * 18;
            int iy = oy0 + r, ix = ox0 + c;
            float v = 0.f;
            if (iy < HW && ix < HW)
                v = xb[(size_t)(ci0 + cl) * (HW * HW) + iy * HW + ix] * ssb[ci0 + cl];
            xs[cl][r][c] = v;
        }
        // load weight tile
        for (int e = t; e < 64 * CI_CHUNK * 9; e += 256) {
            int co  = e / (CI_CHUNK * 9);
            int ck  = e - co * (CI_CHUNK * 9);   // ci*9 + k
            int ci  = ck / 9;
            int k   = ck - ci * 9;
            ws[ck][co] = conv_w[(size_t)(co0 + co) * (CH * 9) + (ci0 + ci) * 9 + k];
        }
        __syncthreads();

#pragma unroll 1
        for (int ci = 0; ci < CI_CHUNK; ci++) {
#pragma unroll
            for (int kh = 0; kh < 3; kh++) {
#pragma unroll
                for (int kw = 0; kw < 3; kw++) {
                    float xr[8];
#pragma unroll
                    for (int j = 0; j < 8; j++)
                        xr[j] = xs[ci][row + kh][col0 + kw + j];
                    int ck = ci * 9 + kh * 3 + kw;
#pragma unroll
                    for (int i = 0; i < 8; i++) {
                        float w = ws[ck][co_base + i];
#pragma unroll
                        for (int j = 0; j < 8; j++)
                            acc[i][j] = fmaf(w, xr[j], acc[i][j]);
                    }
                }
            }
        }
    }

    // epilogue: demod scale + bias
    int oy = oy0 + row;
#pragma unroll
    for (int i = 0; i < 8; i++) {
        int co = co0 + co_base + i;
        float ds = g_dscale[b * CH + co];
        float bias = act_b[co];
        if (oy < OHW) {
            float* orow = g_conv + ((size_t)b * CH + co) * (OHW * OHW) + oy * OHW;
#pragma unroll
            for (int j = 0; j < 8; j++) {
                int ox = ox0 + col0 + j;
                if (ox < OHW) orow[ox] = acc[i][j] * ds + bias;
            }
        }
    }
}

// ----------------------------- filter passes -------------------------------
// upfirdn 1D:  out[o] = sum_t f[taps-1-t] * z[o*down + t],
//   z[j] = in[(j-pad0)/up] when (j-pad0) >= 0, divisible by up, < up*in_len

// horizontal up: [bc][62][62] -> [bc][62][128]   (up=2, pad0=8, gain 2)
__global__ void up_h_kernel(const float* __restrict__ f)
{
    size_t idx = (size_t)blockIdx.x * 256 + threadIdx.x;
    if (idx >= (size_t)BC * OHW * 128) return;
    int o    = (int)(idx & 127);
    size_t r = idx >> 7;                 // bc*62 + y
    const float* row = g_conv + r * OHW;
    float acc = 0.f;
#pragma unroll
    for (int t = 0; t < TAPS; t++) {
        int i = o + t - 8;
        if (i >= 0 && !(i & 1)) {
            int ii = i >> 1;
            if (ii < OHW) acc += f[TAPS - 1 - t] * row[ii];
        }
    }
    g_bufA[idx] = acc * 2.0f;
}

// vertical up: [bc][62][128] -> [bc][128][128]
__global__ void up_v_kernel(const float* __restrict__ f)
{
    size_t idx = (size_t)blockIdx.x * 256 + threadIdx.x;
    if (idx >= (size_t)BC * 128 * 128) return;
    int xcol = (int)(idx & 127);
    int oy   = (int)((idx >> 7) & 127);
    size_t bc = idx >> 14;
    const float* base = g_bufA + bc * (size_t)(OHW * 128);
    float acc = 0.f;
#pragma unroll
    for (int t = 0; t < TAPS; t++) {
        int i = oy + t - 8;
        if (i >= 0 && !(i & 1)) {
            int ii = i >> 1;
            if (ii < OHW) acc += f[TAPS - 1 - t] * base[ii * 128 + xcol];
        }
    }
    g_up2[idx] = acc * 2.0f;
}

// horizontal down (+leaky relu on read): [bc][128][128] -> [bc][128][64]
__global__ void down_h_kernel(const float* __restrict__ f)
{
    size_t idx = (size_t)blockIdx.x * 256 + threadIdx.x;
    if (idx >= (size_t)BC * 128 * 64) return;
    int xo = (int)(idx & 63);
    size_t r = idx >> 6;                 // bc*128 + y
    const float* row = g_up2 + r * 128;
    float acc = 0.f;
#pragma unroll
    for (int t = 0; t < TAPS; t++) {
        int i = 2 * xo + t - 5;
        if (i >= 0 && i < 128) {
            float v = row[i];
            v = (v >= 0.f ? v : NEG_SLOPE * v) * LRELU_SCALE;
            acc += f[TAPS - 1 - t] * v;
        }
    }
    g_bufA[idx] = acc;
}

// vertical down: [bc][128][64] -> [bc][64][64] (final output)
__global__ void down_v_kernel(const float* __restrict__ f,
                              float* __restrict__ out)
{
    size_t idx = (size_t)blockIdx.x * 256 + threadIdx.x;
    if (idx >= (size_t)BC * 64 * 64) return;
    int xcol = (int)(idx & 63);
    int oy   = (int)((idx >> 6) & 63);
    size_t bc = idx >> 12;
    const float* base = g_bufA + bc * (size_t)(128 * 64);
    float acc = 0.f;
#pragma unroll
    for (int t = 0; t < TAPS; t++) {
        int i = 2 * oy + t - 5;
        if (i >= 0 && i < 128) acc += f[TAPS - 1 - t] * base[i * 64 + xcol];
    }
    out[idx] = acc;
}

// ------------------------------ launcher -----------------------------------
extern "C" void kernel_launch(void* const* d_in, const int* in_sizes, int n_in,
                              void* d_out, int out_size)
{
    const float* x        = (const float*)d_in[0];
    const float* style    = (const float*)d_in[1];
    const float* mod_w    = (const float*)d_in[2];
    const float* mod_b    = (const float*)d_in[3];
    const float* conv_w   = (const float*)d_in[4];
    const float* act_b    = (const float*)d_in[5];
    const float* up_filt  = (const float*)d_in[6];
    const float* dn_filt  = (const float*)d_in[7];
    float* out = (float*)d_out;

    mod_kernel<<<BATCH, CH>>>(style, mod_w, mod_b);
    wsq_kernel<<<(CH * CH) / 256, 256>>>(conv_w);
    demod_kernel<<<(BATCH * CH + 127) / 128, 128>>>();

    dim3 cgrid(4, 4, BATCH * 8);
    conv_kernel<<<cgrid, 256>>>(x, conv_w, act_b);

    up_h_kernel  <<<((size_t)BC * OHW * 128) / 256, 256>>>(up_filt);
    up_v_kernel  <<<((size_t)BC * 128 * 128) / 256, 256>>>(up_filt);
    down_h_kernel<<<((size_t)BC * 128 * 64 ) / 256, 256>>>(dn_filt);
    down_v_kernel<<<((size_t)BC * 64  * 64 ) / 256, 256>>>(dn_filt, out);
}